// round 14
// baseline (speedup 1.0000x reference)
#include <cuda_runtime.h>

#define B 32
#define H 512
#define W 512
#define WPR 16                   // 512 bits / 32 = 16 words per row
#define STRIP 16                 // rows per warp (stats)
#define GX (H / STRIP)           // 32 stats row-blocks per batch

#define MINT 46                  // interior rows per medial warp (64 - 2*9 halo)
#define MSTRIPS 12               // ceil(512 / 46)
#define MCOL 4                   // column quarters
#define MWPB 4                   // medial warps per block
#define MGX (MSTRIPS * MCOL / MWPB) // 12 blocks in x
#define MEDIAL_SLICES (B * 2)

// ---- device scratch (no allocations allowed) ----
__device__ unsigned g_pmask[B * H * WPR];
__device__ unsigned g_gmask[B * H * WPR];
__device__ float    g_part[GX][B][12];   // per-CTA stats partials (race-free)
__device__ int      g_msum[B][2];        // medial distance sums  (atomic, reset in finalize)
__device__ int      g_mc  [B][2];        // medial target counts  (atomic, reset in finalize)
__device__ int      g_done_sub[MEDIAL_SLICES];  // per-slice counters (self-resetting)
__device__ int      g_done = 0;          // master counter (self-resetting)

// ======================= stats (unchanged from R13) =======================
struct Raw { float4 v; float eL, eR; };

__device__ __forceinline__ Raw load_raw(const float* __restrict__ rowptr,
                                        int lane, int x0, bool ok) {
    Raw r;
    if (ok) {
        r.v  = *(const float4*)rowptr;
        r.eL = (lane == 0  && x0 > 0)     ? __ldg(rowptr - 1) : 0.f;
        r.eR = (lane == 31 && x0 + 4 < W) ? __ldg(rowptr + 4) : 0.f;
    } else {
        r.v = make_float4(0.f, 0.f, 0.f, 0.f);
        r.eL = r.eR = 0.f;
    }
    return r;
}

struct RowH { float p[4]; float h[4]; };

__device__ __forceinline__ RowH convert(const Raw& r, int lane) {
    float Lp = __shfl_up_sync(0xffffffffu, r.v.w, 1);
    float Rp = __shfl_down_sync(0xffffffffu, r.v.x, 1);
    if (lane == 0)  Lp = r.eL;
    if (lane == 31) Rp = r.eR;
    RowH o;
    o.p[0] = r.v.x; o.p[1] = r.v.y; o.p[2] = r.v.z; o.p[3] = r.v.w;
    o.h[0] = Lp + r.v.x + r.v.y;
    o.h[1] = r.v.x + r.v.y + r.v.z;
    o.h[2] = r.v.y + r.v.z + r.v.w;
    o.h[3] = r.v.z + r.v.w + Rp;
    return o;
}

// gt integer path: per lane compute gon nibble + horizontal triple-sum nibbles
// (htrip nibble i = #ON among cols {i-1,i,i+1}; verified 2-step exact spread).
__device__ __forceinline__ unsigned gt_htrip_nib(const Raw& rg, int lane, unsigned& gnib) {
    unsigned nib = (unsigned)(rg.v.x > 0.5f)
                 | ((unsigned)(rg.v.y > 0.5f) << 1)
                 | ((unsigned)(rg.v.z > 0.5f) << 2)
                 | ((unsigned)(rg.v.w > 0.5f) << 3);
    unsigned upn = __shfl_up_sync(0xffffffffu, nib, 1);
    unsigned dnn = __shfl_down_sync(0xffffffffu, nib, 1);
    unsigned bL = (lane == 0)  ? (unsigned)(rg.eL > 0.5f) : ((upn >> 3) & 1u);
    unsigned bR = (lane == 31) ? (unsigned)(rg.eR > 0.5f) : (dnn & 1u);
    unsigned w6 = bL | (nib << 1) | (bR << 5);
    unsigned t = (w6 | (w6 << 9)) & 0x7007u;             // b0..b2 @0..2, b3..b5 @12..14
    unsigned y = (t | (t << 3) | (t << 6)) & 0x111111u;  // nibble j = b_j exactly
    gnib = nib;
    return (y + (y >> 4) + (y >> 8)) & 0x3333u;          // nib i = b_i+b_{i+1}+b_{i+2}
}

__device__ __forceinline__ unsigned nib_zero(unsigned t) {   // 0x1111-bit per zero nibble
    return 0x1111u & ~(t | (t >> 1) | (t >> 2) | (t >> 3));
}
__device__ __forceinline__ unsigned spread4(unsigned nib) {  // 4 bits -> 0x1111 fields
    return (nib | (nib << 3) | (nib << 6) | (nib << 9)) & 0x1111u;
}

// grid (GX, B), block 128 = 4 warps; pred float stencil + gt integer stencil.
__global__ void __launch_bounds__(128, 6) stats_kernel(const float* __restrict__ pred,
                                                       const float* __restrict__ gt) {
    const int lane = threadIdx.x & 31;
    const int cs   = threadIdx.x >> 5;
    const int b    = blockIdx.y;
    const int y0   = blockIdx.x * STRIP;
    const int x0   = cs * 128 + lane * 4;

    const float* Pp = pred + (size_t)b * H * W + x0 + (size_t)(y0 - 1) * W;
    const float* Gp = gt   + (size_t)b * H * W + x0 + (size_t)(y0 - 1) * W;

    Raw rp  = load_raw(Pp, lane, x0, y0 > 0);      // row y0-1
    Raw rg  = load_raw(Gp, lane, x0, y0 > 0);
    Pp += W; Gp += W;
    Raw rp0 = load_raw(Pp, lane, x0, true);        // row y0
    Raw rg0 = load_raw(Gp, lane, x0, true);
    Pp += W; Gp += W;
    Raw vP1 = load_raw(Pp, lane, x0, y0 + 1 < H);  // row y0+1
    Raw vG1 = load_raw(Gp, lane, x0, y0 + 1 < H);
    Pp += W; Gp += W;
    Raw vP2 = load_raw(Pp, lane, x0, y0 + 2 < H);  // row y0+2
    Raw vG2 = load_raw(Gp, lane, x0, y0 + 2 < H);
    Pp += W; Gp += W;

    RowH ppr = convert(rp, lane);
    float pph[4] = { ppr.h[0], ppr.h[1], ppr.h[2], ppr.h[3] };
    RowH pc = convert(rp0, lane);

    unsigned gnibT;
    unsigned htripP = gt_htrip_nib(rg, lane, gnibT);     // row y0-1
    unsigned gnibC;
    unsigned htripC = gt_htrip_nib(rg0, lane, gnibC);    // row y0

    float a_i = 0.f, a_p = 0.f, a_g = 0.f;
    a_g += rg0.v.x + rg0.v.y + rg0.v.z + rg0.v.w;        // gt sums for row y0
    a_i += rp0.v.x * rg0.v.x + rp0.v.y * rg0.v.y + rp0.v.z * rg0.v.z + rp0.v.w * rg0.v.w;

    int c[9] = {0, 0, 0, 0, 0, 0, 0, 0, 0};

    #pragma unroll 4
    for (int j = 0; j < STRIP; j++) {
        const int y = y0 + j;
        Raw vPn = load_raw(Pp, lane, x0, y + 3 < H);     // row y+3 (consumed 2 iters later)
        Raw vGn = load_raw(Gp, lane, x0, y + 3 < H);
        Pp += W; Gp += W;

        RowH pnx = convert(vP1, lane);                   // pred row y+1

        unsigned gnibN;
        unsigned htripN = gt_htrip_nib(vG1, lane, gnibN); // gt row y+1
        if (j < STRIP - 1) {                              // gt/dice sums for row y+1
            a_g += vG1.v.x + vG1.v.y + vG1.v.z + vG1.v.w;
            a_i += vP1.v.x * vG1.v.x + vP1.v.y * vG1.v.y
                 + vP1.v.z * vG1.v.z + vP1.v.w * vG1.v.w;
        }

        // gt structural for row y (integer, exact)
        unsigned vsum = htripP + htripC + htripN;        // 3x3 sum incl center, <=9/nibble
        unsigned csq  = spread4(gnibC);
        unsigned gcnt = vsum - csq;                      // neighbor count 0..8
        unsigned ge_m = nib_zero(gcnt ^ 0x1111u) & csq;
        unsigned gm_m = nib_zero(gcnt ^ 0x2222u) & csq;
        unsigned gj_m = (((gcnt >> 2) | (gcnt >> 3) | (gcnt & (gcnt >> 1))) & 0x1111u) & csq;

        // pred per-pixel (float stencil)
        unsigned pnib = 0, pe_m = 0, pm_m = 0, pj_m = 0;
        #pragma unroll
        for (int i = 0; i < 4; i++) {
            float pv = pc.p[i];
            float pn = pph[i] + pc.h[i] + pnx.h[i] - pv;
            bool pon = pv > 0.5f;
            unsigned pe = (unsigned)(pon && (pn == 1.f));
            unsigned pm = (unsigned)(pon && (pn == 2.f));
            unsigned pj = (unsigned)(pon && (pn > 2.f));
            a_p += pv;
            pnib |= (unsigned)pon << i;
            pe_m |= pe << (4 * i);
            pm_m |= pm << (4 * i);
            pj_m |= pj << (4 * i);
        }
        c[0] += __popc(pe_m); c[1] += __popc(ge_m); c[2] += __popc(pe_m & ge_m);
        c[3] += __popc(pm_m); c[4] += __popc(gm_m); c[5] += __popc(pm_m & gm_m);
        c[6] += __popc(pj_m); c[7] += __popc(gj_m); c[8] += __popc(pj_m & gj_m);

        // assemble 32-bit mask words over 8-lane nibble groups
        unsigned pw = pnib  << ((lane & 7) * 4);
        unsigned gw = gnibC << ((lane & 7) * 4);
        pw |= __shfl_xor_sync(0xffffffffu, pw, 1);
        gw |= __shfl_xor_sync(0xffffffffu, gw, 1);
        pw |= __shfl_xor_sync(0xffffffffu, pw, 2);
        gw |= __shfl_xor_sync(0xffffffffu, gw, 2);
        pw |= __shfl_xor_sync(0xffffffffu, pw, 4);
        gw |= __shfl_xor_sync(0xffffffffu, gw, 4);
        if ((lane & 7) == 0) {
            size_t widx = (size_t)(b * H + y) * WPR + cs * 4 + (lane >> 3);
            g_pmask[widx] = pw;
            g_gmask[widx] = gw;
        }

        // rotate pipelines
        #pragma unroll
        for (int i = 0; i < 4; i++) pph[i] = pc.h[i];
        pc = pnx;
        htripP = htripC; htripC = htripN; gnibC = gnibN;
        vP1 = vP2; vP2 = vPn;
        vG1 = vG2; vG2 = vGn;
    }

    // warp reduce 12 values
    #pragma unroll
    for (int o = 16; o; o >>= 1) {
        a_i += __shfl_down_sync(0xffffffffu, a_i, o);
        a_p += __shfl_down_sync(0xffffffffu, a_p, o);
        a_g += __shfl_down_sync(0xffffffffu, a_g, o);
    }
    #pragma unroll
    for (int k = 0; k < 9; k++) {
        #pragma unroll
        for (int o = 16; o; o >>= 1) c[k] += __shfl_down_sync(0xffffffffu, c[k], o);
    }

    __shared__ float sf[3];
    __shared__ int   si[9];
    if (threadIdx.x < 3) sf[threadIdx.x] = 0.f;
    if (threadIdx.x < 9) si[threadIdx.x] = 0;
    __syncthreads();
    if (lane == 0) {
        atomicAdd(&sf[0], a_i); atomicAdd(&sf[1], a_p); atomicAdd(&sf[2], a_g);
        #pragma unroll
        for (int k = 0; k < 9; k++) atomicAdd(&si[k], c[k]);
    }
    __syncthreads();
    if (threadIdx.x < 3)  g_part[blockIdx.x][b][threadIdx.x] = sf[threadIdx.x];
    if (threadIdx.x >= 3 && threadIdx.x < 12)
        g_part[blockIdx.x][b][threadIdx.x] = (float)si[threadIdx.x - 3];
}

// ======================= medial: 2 rows/lane, column quarters, early exit =======================
// Each warp owns 64 rows x quarter-row (4 interior words + 1 halo word each side).
// dist_sum = popc(tgt) + sum_d popc(unc_d); unc shrinks monotonically, so once the
// warp's unc is all-zero every remaining round contributes exactly 0 -> break (exact).
// Epilogue: CTA-level smem reduction -> 1 atomic pair per CTA; hierarchical done
// counter (per-slice sub-counter, then master) to avoid single-address serialization.
__device__ __forceinline__ void load_q_row(const unsigned* __restrict__ rowp,
                                           int hq, unsigned* cur) {
    const uint4* q = reinterpret_cast<const uint4*>(rowp);
    uint4 a = q[hq];
    cur[0] = (hq > 0) ? rowp[hq * 4 - 1] : 0u;
    cur[1] = a.x; cur[2] = a.y; cur[3] = a.z; cur[4] = a.w;
    cur[5] = (hq < MCOL - 1) ? rowp[hq * 4 + 4] : 0u;
}
__device__ __forceinline__ void load_q_unc(const unsigned* __restrict__ rowp,
                                           int hq, unsigned* unc) {
    const uint4* q = reinterpret_cast<const uint4*>(rowp);
    uint4 a = q[hq];
    unc[0] = a.x; unc[1] = a.y; unc[2] = a.z; unc[3] = a.w;
}

__global__ void __launch_bounds__(128, 6) medial_kernel(float* __restrict__ out) {
    const int lane = threadIdx.x & 31;
    const int wid  = threadIdx.x >> 5;
    const int sidx = blockIdx.x * MWPB + wid;    // 0..47
    const int strip = sidx >> 2;                 // 0..11 (vertical strip)
    const int hq    = sidx & 3;                  // column quarter
    const int b    = blockIdx.y >> 1;
    const int dir  = blockIdx.y & 1;
    const unsigned* ts = dir ? g_gmask : g_pmask;
    const unsigned* rs = dir ? g_pmask : g_gmask;

    const int base = strip * MINT - 9;
    const int r0 = base + 2 * lane;
    const int r1 = r0 + 1;
    const int i0 = strip * MINT, i1 = i0 + MINT;
    const bool v0 = ((unsigned)r0 < (unsigned)H);
    const bool v1 = ((unsigned)r1 < (unsigned)H);
    const bool in0 = v0 && (r0 >= i0) && (r0 < i1);
    const bool in1 = v1 && (r1 >= i0) && (r1 < i1);

    unsigned cur0[6], cur1[6], unc0[4], unc1[4];
    #pragma unroll
    for (int i = 0; i < 6; i++) { cur0[i] = 0u; cur1[i] = 0u; }
    #pragma unroll
    for (int i = 0; i < 4; i++) { unc0[i] = 0u; unc1[i] = 0u; }

    if (v0)  load_q_row(rs + ((size_t)b * H + r0) * WPR, hq, cur0);
    if (v1)  load_q_row(rs + ((size_t)b * H + r1) * WPR, hq, cur1);
    if (in0) load_q_unc(ts + ((size_t)b * H + r0) * WPR, hq, unc0);
    if (in1) load_q_unc(ts + ((size_t)b * H + r1) * WPR, hq, unc1);

    int cnt = 0, notcov = 0;
    #pragma unroll
    for (int i = 0; i < 4; i++) cnt += __popc(unc0[i]) + __popc(unc1[i]);

    // skip the loop entirely if this warp has no target pixels at all
    unsigned any = unc0[0] | unc0[1] | unc0[2] | unc0[3]
                 | unc1[0] | unc1[1] | unc1[2] | unc1[3];
    if (!__all_sync(0xffffffffu, any == 0u)) {
        for (int d = 1; d <= 9; d++) {
            // horizontal dilation in place (rolling prev)
            unsigned p0 = 0u, p1 = 0u;
            #pragma unroll
            for (int i = 0; i < 6; i++) {
                unsigned o0 = cur0[i], o1 = cur1[i];
                unsigned n0 = (i < 5) ? cur0[i + 1] : 0u;
                unsigned n1 = (i < 5) ? cur1[i + 1] : 0u;
                cur0[i] = o0 | (o0 << 1) | (o0 >> 1) | (p0 >> 31) | (n0 << 31);
                cur1[i] = o1 | (o1 << 1) | (o1 >> 1) | (p1 >> 31) | (n1 << 31);
                p0 = o0; p1 = o1;
            }
            // vertical: own pair in-register, pair boundary via shuffles
            #pragma unroll
            for (int i = 0; i < 6; i++) {
                unsigned h0 = cur0[i], h1 = cur1[i];
                unsigned up = __shfl_up_sync(0xffffffffu, h1, 1);
                unsigned dn = __shfl_down_sync(0xffffffffu, h0, 1);
                up = (lane == 0)  ? 0u : up;
                dn = (lane == 31) ? 0u : dn;
                cur0[i] = h0 | up | h1;
                cur1[i] = h1 | h0 | dn;
            }
            // uncovered-set shrink (interior words are cur[1..4])
            any = 0u;
            #pragma unroll
            for (int i = 0; i < 4; i++) {
                unc0[i] &= ~cur0[i + 1];
                unc1[i] &= ~cur1[i + 1];
                notcov += __popc(unc0[i]) + __popc(unc1[i]);
                any |= unc0[i] | unc1[i];
            }
            // all remaining rounds contribute 0 once unc == 0 warp-wide (monotone shrink)
            if (__all_sync(0xffffffffu, any == 0u)) break;
        }
    }

    // warp reduce, then CTA reduce in smem (all warps share (b,dir))
    int dist = cnt + notcov;
    #pragma unroll
    for (int o = 16; o; o >>= 1) {
        dist += __shfl_down_sync(0xffffffffu, dist, o);
        cnt  += __shfl_down_sync(0xffffffffu, cnt, o);
    }
    __shared__ int sred[MWPB][2];
    if (lane == 0) { sred[wid][0] = dist; sred[wid][1] = cnt; }
    __syncthreads();

    __shared__ bool isLast;
    if (threadIdx.x == 0) {
        int D = sred[0][0] + sred[1][0] + sred[2][0] + sred[3][0];
        int C = sred[0][1] + sred[1][1] + sred[2][1] + sred[3][1];
        atomicAdd(&g_msum[b][dir], D);
        atomicAdd(&g_mc[b][dir], C);
        __threadfence();
        // hierarchical completion: per-slice counter first, master only once per slice
        bool last = false;
        int so = atomicAdd(&g_done_sub[blockIdx.y], 1);
        if (so == MGX - 1) {
            g_done_sub[blockIdx.y] = 0;          // reset for next graph replay
            __threadfence();
            int mo = atomicAdd(&g_done, 1);
            last = (mo == MEDIAL_SLICES - 1);
        }
        isLast = last;
    }
    __syncthreads();
    if (!isLast) return;
    __threadfence();

    __shared__ float acc[B][12];
    __shared__ float sd[B], ss[B], sm2[B];
    int t = threadIdx.x;
    for (int idx = t; idx < B * 12; idx += 128) {
        int bb = idx / 12, k = idx % 12;
        float s = 0.f;
        #pragma unroll
        for (int i = 0; i < GX; i++) s += g_part[i][bb][k];
        acc[bb][k] = s;
    }
    __syncthreads();

    if (t < B) {
        int bb = t;
        float inter = acc[bb][0], ps = acc[bb][1], gs = acc[bb][2];
        float dice = (2.f * inter + 1.f) / (ps + gs + 1.f);

        float pe = acc[bb][3],  ge = acc[bb][4],  ie = acc[bb][5];
        float pm = acc[bb][6],  gm = acc[bb][7],  im = acc[bb][8];
        float pj = acc[bb][9],  gj = acc[bb][10], ij = acc[bb][11];
        float e_iou = (ie + 1.f) / (pe + ge - ie + 1.f);
        float m_iou = (im + 1.f) / (pm + gm - im + 1.f);
        float j_iou = (ij + 1.f) / (pj + gj - ij + 1.f);
        float total = ge + gj + gm + 1.f;
        float sl = 1.f - ((ge / total) * e_iou + (gj / total) * j_iou + (gm / total) * m_iou);

        float p2g = (float)g_msum[bb][0] / ((float)g_mc[bb][0] + 1.f);
        float g2p = (float)g_msum[bb][1] / ((float)g_mc[bb][1] + 1.f);
        float med = ((p2g + g2p) * 0.5f) / 10.f;

        sd[bb] = dice; ss[bb] = sl; sm2[bb] = med;
    }
    __syncthreads();

    // reset accumulators for the next graph replay
    if (t < B * 2) {
        ((int*)g_msum)[t] = 0;
        ((int*)g_mc)[t]   = 0;
    }

    if (t == 0) {
        float d = 0.f, s = 0.f, m = 0.f;
        for (int i = 0; i < B; i++) { d += sd[i]; s += ss[i]; m += sm2[i]; }
        d *= (1.f / B); s *= (1.f / B); m *= (1.f / B);
        float dl = 1.f - d;
        float avg = (dl + s + m) / 3.f;
        out[0] = dl / (dl + 1.f) * avg + s / (s + 1.f) * avg + m / (m + 1.f) * avg;
        g_done = 0;                              // reset for next graph replay
    }
}

extern "C" void kernel_launch(void* const* d_in, const int* in_sizes, int n_in,
                              void* d_out, int out_size) {
    const float* pred = (const float*)d_in[0];
    const float* gt   = (const float*)d_in[1];
    float* out = (float*)d_out;
    (void)in_sizes; (void)n_in; (void)out_size;

    stats_kernel<<<dim3(GX, B), 128>>>(pred, gt);
    medial_kernel<<<dim3(MGX, B * 2), 128>>>(out);
}

// round 15
// speedup vs baseline: 1.0378x; 1.0378x over previous
#include <cuda_runtime.h>

#define B 32
#define H 512
#define W 512
#define WPR 16                   // 512 bits / 32 = 16 words per row
#define STRIP 16                 // rows per warp (stats)
#define GX (H / STRIP)           // 32 stats row-blocks per batch

#define MINT 46                  // interior rows per medial warp (64 - 2*9 halo)
#define MSTRIPS 12               // ceil(512 / 46)
#define MCOL 4                   // column quarters
#define MWPB 2                   // medial warps per block
#define MTHR (MWPB * 32)         // 64 threads
#define MGX (MSTRIPS * MCOL / MWPB) // 24 blocks in x
#define MEDIAL_BLOCKS (MGX * B * 2)

// ---- device scratch (no allocations allowed) ----
__device__ unsigned g_pmask[B * H * WPR];
__device__ unsigned g_gmask[B * H * WPR];
__device__ float    g_part[GX][B][2];    // race-free float partials: [0]=a_i, [1]=a_p
__device__ int      g_icnt[B][10];       // int counters (atomic, exact): 0..8 = pe,ge,ie,pm,gm,im,pj,gj,ij; 9 = gt count
__device__ int      g_msum[B][2];        // medial distance sums  (atomic, reset in finalize)
__device__ int      g_mc  [B][2];        // medial target counts  (atomic, reset in finalize)
__device__ int      g_done = 0;          // last-block counter (self-resetting)

// ======================= stats =======================
struct Raw { float4 v; float eL, eR; };

__device__ __forceinline__ Raw load_raw(const float* __restrict__ rowptr,
                                        int lane, int x0, bool ok) {
    Raw r;
    if (ok) {
        r.v  = *(const float4*)rowptr;
        r.eL = (lane == 0  && x0 > 0)     ? __ldg(rowptr - 1) : 0.f;
        r.eR = (lane == 31 && x0 + 4 < W) ? __ldg(rowptr + 4) : 0.f;
    } else {
        r.v = make_float4(0.f, 0.f, 0.f, 0.f);
        r.eL = r.eR = 0.f;
    }
    return r;
}

struct RowH { float p[4]; float h[4]; };

__device__ __forceinline__ RowH convert(const Raw& r, int lane) {
    float Lp = __shfl_up_sync(0xffffffffu, r.v.w, 1);
    float Rp = __shfl_down_sync(0xffffffffu, r.v.x, 1);
    if (lane == 0)  Lp = r.eL;
    if (lane == 31) Rp = r.eR;
    RowH o;
    o.p[0] = r.v.x; o.p[1] = r.v.y; o.p[2] = r.v.z; o.p[3] = r.v.w;
    o.h[0] = Lp + r.v.x + r.v.y;
    o.h[1] = r.v.x + r.v.y + r.v.z;
    o.h[2] = r.v.y + r.v.z + r.v.w;
    o.h[3] = r.v.z + r.v.w + Rp;
    return o;
}

// gt integer path: per lane compute gon nibble + horizontal triple-sum nibbles
// (htrip nibble i = #ON among cols {i-1,i,i+1}; verified 2-step exact spread).
__device__ __forceinline__ unsigned gt_htrip_nib(const Raw& rg, int lane, unsigned& gnib) {
    unsigned nib = (unsigned)(rg.v.x > 0.5f)
                 | ((unsigned)(rg.v.y > 0.5f) << 1)
                 | ((unsigned)(rg.v.z > 0.5f) << 2)
                 | ((unsigned)(rg.v.w > 0.5f) << 3);
    unsigned upn = __shfl_up_sync(0xffffffffu, nib, 1);
    unsigned dnn = __shfl_down_sync(0xffffffffu, nib, 1);
    unsigned bL = (lane == 0)  ? (unsigned)(rg.eL > 0.5f) : ((upn >> 3) & 1u);
    unsigned bR = (lane == 31) ? (unsigned)(rg.eR > 0.5f) : (dnn & 1u);
    unsigned w6 = bL | (nib << 1) | (bR << 5);
    unsigned t = (w6 | (w6 << 9)) & 0x7007u;             // b0..b2 @0..2, b3..b5 @12..14
    unsigned y = (t | (t << 3) | (t << 6)) & 0x111111u;  // nibble j = b_j exactly
    gnib = nib;
    return (y + (y >> 4) + (y >> 8)) & 0x3333u;          // nib i = b_i+b_{i+1}+b_{i+2}
}

__device__ __forceinline__ unsigned nib_zero(unsigned t) {   // 0x1111-bit per zero nibble
    return 0x1111u & ~(t | (t >> 1) | (t >> 2) | (t >> 3));
}
__device__ __forceinline__ unsigned spread4(unsigned nib) {  // 4 bits -> 0x1111 fields
    return (nib | (nib << 3) | (nib << 6) | (nib << 9)) & 0x1111u;
}

// grid (GX, B), block 128 = 4 warps; pred float stencil + gt integer stencil.
__global__ void __launch_bounds__(128, 6) stats_kernel(const float* __restrict__ pred,
                                                       const float* __restrict__ gt) {
    const int lane = threadIdx.x & 31;
    const int cs   = threadIdx.x >> 5;
    const int b    = blockIdx.y;
    const int y0   = blockIdx.x * STRIP;
    const int x0   = cs * 128 + lane * 4;

    const float* Pp = pred + (size_t)b * H * W + x0 + (size_t)(y0 - 1) * W;
    const float* Gp = gt   + (size_t)b * H * W + x0 + (size_t)(y0 - 1) * W;

    Raw rp  = load_raw(Pp, lane, x0, y0 > 0);      // row y0-1
    Raw rg  = load_raw(Gp, lane, x0, y0 > 0);
    Pp += W; Gp += W;
    Raw rp0 = load_raw(Pp, lane, x0, true);        // row y0
    Raw rg0 = load_raw(Gp, lane, x0, true);
    Pp += W; Gp += W;
    Raw vP1 = load_raw(Pp, lane, x0, y0 + 1 < H);  // row y0+1
    Raw vG1 = load_raw(Gp, lane, x0, y0 + 1 < H);
    Pp += W; Gp += W;
    Raw vP2 = load_raw(Pp, lane, x0, y0 + 2 < H);  // row y0+2
    Raw vG2 = load_raw(Gp, lane, x0, y0 + 2 < H);
    Pp += W; Gp += W;

    RowH ppr = convert(rp, lane);
    float pph[4] = { ppr.h[0], ppr.h[1], ppr.h[2], ppr.h[3] };
    RowH pc = convert(rp0, lane);

    unsigned gnibT;
    unsigned htripP = gt_htrip_nib(rg, lane, gnibT);     // row y0-1
    unsigned gnibC;
    unsigned htripC = gt_htrip_nib(rg0, lane, gnibC);    // row y0

    float a_i = 0.f, a_p = 0.f;
    a_i += rp0.v.x * rg0.v.x + rp0.v.y * rg0.v.y + rp0.v.z * rg0.v.z + rp0.v.w * rg0.v.w;

    int c[10] = {0, 0, 0, 0, 0, 0, 0, 0, 0, 0};   // [9] = gt ON count

    #pragma unroll 4
    for (int j = 0; j < STRIP; j++) {
        const int y = y0 + j;
        Raw vPn = load_raw(Pp, lane, x0, y + 3 < H);     // row y+3 (consumed 2 iters later)
        Raw vGn = load_raw(Gp, lane, x0, y + 3 < H);
        Pp += W; Gp += W;

        RowH pnx = convert(vP1, lane);                   // pred row y+1

        unsigned gnibN;
        unsigned htripN = gt_htrip_nib(vG1, lane, gnibN); // gt row y+1
        if (j < STRIP - 1) {                              // dice intersection for row y+1
            a_i += vP1.v.x * vG1.v.x + vP1.v.y * vG1.v.y
                 + vP1.v.z * vG1.v.z + vP1.v.w * vG1.v.w;
        }

        // gt structural for row y (integer, exact)
        unsigned vsum = htripP + htripC + htripN;        // 3x3 sum incl center, <=9/nibble
        unsigned csq  = spread4(gnibC);
        unsigned gcnt = vsum - csq;                      // neighbor count 0..8
        unsigned ge_m = nib_zero(gcnt ^ 0x1111u) & csq;
        unsigned gm_m = nib_zero(gcnt ^ 0x2222u) & csq;
        unsigned gj_m = (((gcnt >> 2) | (gcnt >> 3) | (gcnt & (gcnt >> 1))) & 0x1111u) & csq;
        c[9] += __popc(gnibC);                           // gt ON count (exact int)

        // pred per-pixel (float stencil)
        unsigned pnib = 0, pe_m = 0, pm_m = 0, pj_m = 0;
        #pragma unroll
        for (int i = 0; i < 4; i++) {
            float pv = pc.p[i];
            float pn = pph[i] + pc.h[i] + pnx.h[i] - pv;
            bool pon = pv > 0.5f;
            unsigned pe = (unsigned)(pon && (pn == 1.f));
            unsigned pm = (unsigned)(pon && (pn == 2.f));
            unsigned pj = (unsigned)(pon && (pn > 2.f));
            a_p += pv;
            pnib |= (unsigned)pon << i;
            pe_m |= pe << (4 * i);
            pm_m |= pm << (4 * i);
            pj_m |= pj << (4 * i);
        }
        c[0] += __popc(pe_m); c[1] += __popc(ge_m); c[2] += __popc(pe_m & ge_m);
        c[3] += __popc(pm_m); c[4] += __popc(gm_m); c[5] += __popc(pm_m & gm_m);
        c[6] += __popc(pj_m); c[7] += __popc(gj_m); c[8] += __popc(pj_m & gj_m);

        // assemble 32-bit mask words over 8-lane nibble groups
        unsigned pw = pnib  << ((lane & 7) * 4);
        unsigned gw = gnibC << ((lane & 7) * 4);
        pw |= __shfl_xor_sync(0xffffffffu, pw, 1);
        gw |= __shfl_xor_sync(0xffffffffu, gw, 1);
        pw |= __shfl_xor_sync(0xffffffffu, pw, 2);
        gw |= __shfl_xor_sync(0xffffffffu, gw, 2);
        pw |= __shfl_xor_sync(0xffffffffu, pw, 4);
        gw |= __shfl_xor_sync(0xffffffffu, gw, 4);
        if ((lane & 7) == 0) {
            size_t widx = (size_t)(b * H + y) * WPR + cs * 4 + (lane >> 3);
            g_pmask[widx] = pw;
            g_gmask[widx] = gw;
        }

        // rotate pipelines
        #pragma unroll
        for (int i = 0; i < 4; i++) pph[i] = pc.h[i];
        pc = pnx;
        htripP = htripC; htripC = htripN; gnibC = gnibN;
        vP1 = vP2; vP2 = vPn;
        vG1 = vG2; vG2 = vGn;
    }

    // warp reduce
    #pragma unroll
    for (int o = 16; o; o >>= 1) {
        a_i += __shfl_down_sync(0xffffffffu, a_i, o);
        a_p += __shfl_down_sync(0xffffffffu, a_p, o);
    }
    #pragma unroll
    for (int k = 0; k < 10; k++) {
        #pragma unroll
        for (int o = 16; o; o >>= 1) c[k] += __shfl_down_sync(0xffffffffu, c[k], o);
    }

    __shared__ float sf[2];
    __shared__ int   si[10];
    if (threadIdx.x < 2)  sf[threadIdx.x] = 0.f;
    if (threadIdx.x < 10) si[threadIdx.x] = 0;
    __syncthreads();
    if (lane == 0) {
        atomicAdd(&sf[0], a_i); atomicAdd(&sf[1], a_p);
        #pragma unroll
        for (int k = 0; k < 10; k++) atomicAdd(&si[k], c[k]);
    }
    __syncthreads();
    if (threadIdx.x < 2)  g_part[blockIdx.x][b][threadIdx.x] = sf[threadIdx.x];
    if (threadIdx.x >= 2 && threadIdx.x < 12)
        atomicAdd(&g_icnt[b][threadIdx.x - 2], si[threadIdx.x - 2]);   // exact int, order-free
}

// ======================= medial: 2 rows/lane, column quarters, early exit =======================
// Each warp owns 64 rows x quarter-row (4 interior words + 1 halo word each side).
// dist_sum = popc(tgt) + sum_d popc(unc_d); unc shrinks monotonically, so once the
// warp's unc is all-zero every remaining round contributes exactly 0 -> break (exact).
__device__ __forceinline__ void load_q_row(const unsigned* __restrict__ rowp,
                                           int hq, unsigned* cur) {
    const uint4* q = reinterpret_cast<const uint4*>(rowp);
    uint4 a = q[hq];
    cur[0] = (hq > 0) ? rowp[hq * 4 - 1] : 0u;
    cur[1] = a.x; cur[2] = a.y; cur[3] = a.z; cur[4] = a.w;
    cur[5] = (hq < MCOL - 1) ? rowp[hq * 4 + 4] : 0u;
}
__device__ __forceinline__ void load_q_unc(const unsigned* __restrict__ rowp,
                                           int hq, unsigned* unc) {
    const uint4* q = reinterpret_cast<const uint4*>(rowp);
    uint4 a = q[hq];
    unc[0] = a.x; unc[1] = a.y; unc[2] = a.z; unc[3] = a.w;
}

__global__ void __launch_bounds__(MTHR, 12) medial_kernel(float* __restrict__ out) {
    const int lane = threadIdx.x & 31;
    const int wid  = threadIdx.x >> 5;
    const int sidx = blockIdx.x * MWPB + wid;    // 0..47
    const int strip = sidx >> 2;                 // 0..11 (vertical strip)
    const int hq    = sidx & 3;                  // column quarter
    const int b    = blockIdx.y >> 1;
    const int dir  = blockIdx.y & 1;
    const unsigned* ts = dir ? g_gmask : g_pmask;
    const unsigned* rs = dir ? g_pmask : g_gmask;

    const int base = strip * MINT - 9;
    const int r0 = base + 2 * lane;
    const int r1 = r0 + 1;
    const int i0 = strip * MINT, i1 = i0 + MINT;
    const bool v0 = ((unsigned)r0 < (unsigned)H);
    const bool v1 = ((unsigned)r1 < (unsigned)H);
    const bool in0 = v0 && (r0 >= i0) && (r0 < i1);
    const bool in1 = v1 && (r1 >= i0) && (r1 < i1);

    unsigned cur0[6], cur1[6], unc0[4], unc1[4];
    #pragma unroll
    for (int i = 0; i < 6; i++) { cur0[i] = 0u; cur1[i] = 0u; }
    #pragma unroll
    for (int i = 0; i < 4; i++) { unc0[i] = 0u; unc1[i] = 0u; }

    if (v0)  load_q_row(rs + ((size_t)b * H + r0) * WPR, hq, cur0);
    if (v1)  load_q_row(rs + ((size_t)b * H + r1) * WPR, hq, cur1);
    if (in0) load_q_unc(ts + ((size_t)b * H + r0) * WPR, hq, unc0);
    if (in1) load_q_unc(ts + ((size_t)b * H + r1) * WPR, hq, unc1);

    int cnt = 0, notcov = 0;
    #pragma unroll
    for (int i = 0; i < 4; i++) cnt += __popc(unc0[i]) + __popc(unc1[i]);

    // skip the loop entirely if this warp has no target pixels at all
    unsigned any = unc0[0] | unc0[1] | unc0[2] | unc0[3]
                 | unc1[0] | unc1[1] | unc1[2] | unc1[3];
    if (!__all_sync(0xffffffffu, any == 0u)) {
        for (int d = 1; d <= 9; d++) {
            // horizontal dilation in place (rolling prev)
            unsigned p0 = 0u, p1 = 0u;
            #pragma unroll
            for (int i = 0; i < 6; i++) {
                unsigned o0 = cur0[i], o1 = cur1[i];
                unsigned n0 = (i < 5) ? cur0[i + 1] : 0u;
                unsigned n1 = (i < 5) ? cur1[i + 1] : 0u;
                cur0[i] = o0 | (o0 << 1) | (o0 >> 1) | (p0 >> 31) | (n0 << 31);
                cur1[i] = o1 | (o1 << 1) | (o1 >> 1) | (p1 >> 31) | (n1 << 31);
                p0 = o0; p1 = o1;
            }
            // vertical: own pair in-register, pair boundary via shuffles
            #pragma unroll
            for (int i = 0; i < 6; i++) {
                unsigned h0 = cur0[i], h1 = cur1[i];
                unsigned up = __shfl_up_sync(0xffffffffu, h1, 1);
                unsigned dn = __shfl_down_sync(0xffffffffu, h0, 1);
                up = (lane == 0)  ? 0u : up;
                dn = (lane == 31) ? 0u : dn;
                cur0[i] = h0 | up | h1;
                cur1[i] = h1 | h0 | dn;
            }
            // uncovered-set shrink (interior words are cur[1..4])
            any = 0u;
            #pragma unroll
            for (int i = 0; i < 4; i++) {
                unc0[i] &= ~cur0[i + 1];
                unc1[i] &= ~cur1[i + 1];
                notcov += __popc(unc0[i]) + __popc(unc1[i]);
                any |= unc0[i] | unc1[i];
            }
            // all remaining rounds contribute 0 once unc == 0 warp-wide (monotone shrink)
            if (__all_sync(0xffffffffu, any == 0u)) break;
        }
    }

    // warp reduce, then CTA reduce in smem (both warps share (b,dir))
    int dist = cnt + notcov;
    #pragma unroll
    for (int o = 16; o; o >>= 1) {
        dist += __shfl_down_sync(0xffffffffu, dist, o);
        cnt  += __shfl_down_sync(0xffffffffu, cnt, o);
    }
    __shared__ int sred[MWPB][2];
    if (lane == 0) { sred[wid][0] = dist; sred[wid][1] = cnt; }
    __syncthreads();

    __shared__ bool isLast;
    if (threadIdx.x == 0) {
        int D = sred[0][0] + sred[1][0];
        int C = sred[0][1] + sred[1][1];
        atomicAdd(&g_msum[b][dir], D);
        atomicAdd(&g_mc[b][dir], C);
        __threadfence();
        int old = atomicAdd(&g_done, 1);
        isLast = (old == MEDIAL_BLOCKS - 1);
    }
    __syncthreads();
    if (!isLast) return;
    __threadfence();

    // ---- fused finalize (64 threads) ----
    __shared__ float accf[B][2];
    __shared__ float sd[B], ss[B], sm2[B];
    int t = threadIdx.x;
    {
        int bb = t >> 1, k = t & 1;          // 64 threads cover B*2 entries exactly
        float s = 0.f;
        #pragma unroll
        for (int i = 0; i < GX; i++) s += g_part[i][bb][k];
        accf[bb][k] = s;
    }
    __syncthreads();

    if (t < B) {
        int bb = t;
        float inter = accf[bb][0], ps = accf[bb][1];
        float gs = (float)g_icnt[bb][9];
        float dice = (2.f * inter + 1.f) / (ps + gs + 1.f);

        float pe = (float)g_icnt[bb][0], ge = (float)g_icnt[bb][1], ie = (float)g_icnt[bb][2];
        float pm = (float)g_icnt[bb][3], gm = (float)g_icnt[bb][4], im = (float)g_icnt[bb][5];
        float pj = (float)g_icnt[bb][6], gj = (float)g_icnt[bb][7], ij = (float)g_icnt[bb][8];
        float e_iou = (ie + 1.f) / (pe + ge - ie + 1.f);
        float m_iou = (im + 1.f) / (pm + gm - im + 1.f);
        float j_iou = (ij + 1.f) / (pj + gj - ij + 1.f);
        float total = ge + gj + gm + 1.f;
        float sl = 1.f - ((ge / total) * e_iou + (gj / total) * j_iou + (gm / total) * m_iou);

        float p2g = (float)g_msum[bb][0] / ((float)g_mc[bb][0] + 1.f);
        float g2p = (float)g_msum[bb][1] / ((float)g_mc[bb][1] + 1.f);
        float med = ((p2g + g2p) * 0.5f) / 10.f;

        sd[bb] = dice; ss[bb] = sl; sm2[bb] = med;
    }
    __syncthreads();

    // reset accumulators for the next graph replay (after all reads)
    for (int idx = t; idx < B * 10; idx += MTHR) ((int*)g_icnt)[idx] = 0;
    ((int*)g_msum)[t] = 0;     // t covers B*2 = 64 exactly
    ((int*)g_mc)[t]   = 0;

    if (t == 0) {
        float d = 0.f, s = 0.f, m = 0.f;
        for (int i = 0; i < B; i++) { d += sd[i]; s += ss[i]; m += sm2[i]; }
        d *= (1.f / B); s *= (1.f / B); m *= (1.f / B);
        float dl = 1.f - d;
        float avg = (dl + s + m) / 3.f;
        out[0] = dl / (dl + 1.f) * avg + s / (s + 1.f) * avg + m / (m + 1.f) * avg;
        g_done = 0;                              // reset for next graph replay
    }
}

extern "C" void kernel_launch(void* const* d_in, const int* in_sizes, int n_in,
                              void* d_out, int out_size) {
    const float* pred = (const float*)d_in[0];
    const float* gt   = (const float*)d_in[1];
    float* out = (float*)d_out;
    (void)in_sizes; (void)n_in; (void)out_size;

    stats_kernel<<<dim3(GX, B), 128>>>(pred, gt);
    medial_kernel<<<dim3(MGX, B * 2), MTHR>>>(out);
}

// round 16
// speedup vs baseline: 1.0785x; 1.0393x over previous
#include <cuda_runtime.h>

#define B 32
#define H 512
#define W 512
#define WPR 16                   // 512 bits / 32 = 16 words per row
#define STRIP 16                 // rows per warp (stats)
#define GX (H / STRIP)           // 32 stats row-blocks per batch

#define MINT 46                  // interior rows per medial warp (64 - 2*9 halo)
#define MSTRIPS 12               // ceil(512 / 46)
#define MCOL 4                   // column quarters
#define MWPB 2                   // medial warps per block
#define MTHR (MWPB * 32)         // 64 threads
#define MGX (MSTRIPS * MCOL / MWPB) // 24 blocks in x
#define MEDIAL_BLOCKS (MGX * B * 2)

// ---- device scratch (no allocations allowed) ----
__device__ unsigned g_pmask[B * H * WPR];
__device__ unsigned g_gmask[B * H * WPR];
__device__ float    g_part[GX][B][2];    // race-free float partials: [0]=a_i, [1]=a_p
__device__ int      g_icnt[B][10];       // int counters (atomic, exact)
__device__ int      g_msum[B][2];        // medial distance sums
__device__ int      g_mc  [B][2];        // medial target counts
__device__ int      g_done = 0;          // last-block counter (self-resetting)

// ======================= f32x2 packed helpers (sm_103a) =======================
typedef unsigned long long ull;

__device__ __forceinline__ ull f2x_pack(float lo, float hi) {
    ull r;
    asm("mov.b64 %0, {%1, %2};" : "=l"(r)
        : "r"(__float_as_uint(lo)), "r"(__float_as_uint(hi)));
    return r;
}
__device__ __forceinline__ ull f2x_add(ull a, ull b) {
    ull d;
    asm("add.rn.f32x2 %0, %1, %2;" : "=l"(d) : "l"(a), "l"(b));
    return d;
}
__device__ __forceinline__ ull f2x_fma(ull a, ull b, ull c) {
    ull d;
    asm("fma.rn.f32x2 %0, %1, %2, %3;" : "=l"(d) : "l"(a), "l"(b), "l"(c));
    return d;
}
__device__ __forceinline__ void f2x_unpack(ull v, float& lo, float& hi) {
    unsigned l, h;
    asm("mov.b64 {%0, %1}, %2;" : "=r"(l), "=r"(h) : "l"(v));
    lo = __uint_as_float(l); hi = __uint_as_float(h);
}
#define NEG1_F2X 0xBF800000BF800000ULL   // (-1.f, -1.f)

// ======================= stats =======================
struct Raw { float4 v; float eL, eR; };

__device__ __forceinline__ Raw load_raw(const float* __restrict__ rowptr,
                                        int lane, int x0, bool ok) {
    Raw r;
    if (ok) {
        r.v  = *(const float4*)rowptr;
        r.eL = (lane == 0  && x0 > 0)     ? __ldg(rowptr - 1) : 0.f;
        r.eR = (lane == 31 && x0 + 4 < W) ? __ldg(rowptr + 4) : 0.f;
    } else {
        r.v = make_float4(0.f, 0.f, 0.f, 0.f);
        r.eL = r.eR = 0.f;
    }
    return r;
}

struct RowF2 { ull h01, h23, p01, p23; };

// Packed horizontal triple sums; component rounding order identical to scalar:
// h0=(Lp+p0)+p1, h1=(p0+p1)+p2, h2=(p1+p2)+p3, h3=(p2+p3)+Rp.
__device__ __forceinline__ RowF2 convert2(const Raw& r, int lane) {
    float Lp = __shfl_up_sync(0xffffffffu, r.v.w, 1);
    float Rp = __shfl_down_sync(0xffffffffu, r.v.x, 1);
    if (lane == 0)  Lp = r.eL;
    if (lane == 31) Rp = r.eR;
    RowF2 o;
    o.p01 = f2x_pack(r.v.x, r.v.y);
    o.p23 = f2x_pack(r.v.z, r.v.w);
    ull tA = f2x_pack(Lp, r.v.x);
    ull tM = f2x_pack(r.v.y, r.v.z);
    ull tB = f2x_pack(r.v.w, Rp);
    o.h01 = f2x_add(f2x_add(tA, o.p01), tM);
    o.h23 = f2x_add(f2x_add(tM, o.p23), tB);
    return o;
}

// gt integer path (verified 2-step exact spread).
__device__ __forceinline__ unsigned gt_htrip_nib(const Raw& rg, int lane, unsigned& gnib) {
    unsigned nib = (unsigned)(rg.v.x > 0.5f)
                 | ((unsigned)(rg.v.y > 0.5f) << 1)
                 | ((unsigned)(rg.v.z > 0.5f) << 2)
                 | ((unsigned)(rg.v.w > 0.5f) << 3);
    unsigned upn = __shfl_up_sync(0xffffffffu, nib, 1);
    unsigned dnn = __shfl_down_sync(0xffffffffu, nib, 1);
    unsigned bL = (lane == 0)  ? (unsigned)(rg.eL > 0.5f) : ((upn >> 3) & 1u);
    unsigned bR = (lane == 31) ? (unsigned)(rg.eR > 0.5f) : (dnn & 1u);
    unsigned w6 = bL | (nib << 1) | (bR << 5);
    unsigned t = (w6 | (w6 << 9)) & 0x7007u;
    unsigned y = (t | (t << 3) | (t << 6)) & 0x111111u;
    gnib = nib;
    return (y + (y >> 4) + (y >> 8)) & 0x3333u;
}

__device__ __forceinline__ unsigned nib_zero(unsigned t) {
    return 0x1111u & ~(t | (t >> 1) | (t >> 2) | (t >> 3));
}
__device__ __forceinline__ unsigned spread4(unsigned nib) {
    return (nib | (nib << 3) | (nib << 6) | (nib << 9)) & 0x1111u;
}
__device__ __forceinline__ unsigned pon_nib(const Raw& r) {
    return (unsigned)(r.v.x > 0.5f)
         | ((unsigned)(r.v.y > 0.5f) << 1)
         | ((unsigned)(r.v.z > 0.5f) << 2)
         | ((unsigned)(r.v.w > 0.5f) << 3);
}

// grid (GX, B), block 128 = 4 warps; packed-f32x2 pred stencil + int gt stencil.
__global__ void __launch_bounds__(128, 6) stats_kernel(const float* __restrict__ pred,
                                                       const float* __restrict__ gt) {
    const int lane = threadIdx.x & 31;
    const int cs   = threadIdx.x >> 5;
    const int b    = blockIdx.y;
    const int y0   = blockIdx.x * STRIP;
    const int x0   = cs * 128 + lane * 4;

    const float* Pp = pred + (size_t)b * H * W + x0 + (size_t)(y0 - 1) * W;
    const float* Gp = gt   + (size_t)b * H * W + x0 + (size_t)(y0 - 1) * W;

    Raw rp  = load_raw(Pp, lane, x0, y0 > 0);      // row y0-1
    Raw rg  = load_raw(Gp, lane, x0, y0 > 0);
    Pp += W; Gp += W;
    Raw rp0 = load_raw(Pp, lane, x0, true);        // row y0
    Raw rg0 = load_raw(Gp, lane, x0, true);
    Pp += W; Gp += W;
    Raw vP1 = load_raw(Pp, lane, x0, y0 + 1 < H);  // row y0+1
    Raw vG1 = load_raw(Gp, lane, x0, y0 + 1 < H);
    Pp += W; Gp += W;

    RowF2 pr = convert2(rp, lane);
    ull ph01 = pr.h01, ph23 = pr.h23;              // prev-row h
    RowF2 cr = convert2(rp0, lane);
    ull ch01 = cr.h01, ch23 = cr.h23;              // current-row h
    ull cp01 = cr.p01, cp23 = cr.p23;              // current-row values
    ull cg01 = f2x_pack(rg0.v.x, rg0.v.y);
    ull cg23 = f2x_pack(rg0.v.z, rg0.v.w);
    unsigned pnibC = pon_nib(rp0);

    unsigned gnibT;
    unsigned htripP = gt_htrip_nib(rg, lane, gnibT);     // row y0-1
    unsigned gnibC;
    unsigned htripC = gt_htrip_nib(rg0, lane, gnibC);    // row y0

    ull ai01 = 0ull, ai23 = 0ull, ap01 = 0ull, ap23 = 0ull;
    int c[10] = {0, 0, 0, 0, 0, 0, 0, 0, 0, 0};

    #pragma unroll 4
    for (int j = 0; j < STRIP; j++) {
        const int y = y0 + j;
        Raw vPn = load_raw(Pp, lane, x0, y + 2 < H);     // row y+2 (consumed next iter)
        Raw vGn = load_raw(Gp, lane, x0, y + 2 < H);
        Pp += W; Gp += W;

        RowF2 nx = convert2(vP1, lane);                  // pred row y+1
        unsigned pnibN = pon_nib(vP1);
        unsigned gnibN;
        unsigned htripN = gt_htrip_nib(vG1, lane, gnibN); // gt row y+1
        ull ng01 = f2x_pack(vG1.v.x, vG1.v.y);
        ull ng23 = f2x_pack(vG1.v.z, vG1.v.w);

        // dice sums for current row (packed; per-component rounding = scalar)
        ai01 = f2x_fma(cp01, cg01, ai01);
        ai23 = f2x_fma(cp23, cg23, ai23);
        ap01 = f2x_add(ap01, cp01);
        ap23 = f2x_add(ap23, cp23);
        c[9] += __popc(gnibC);

        // pred neighbor sums: pn = (ph+ch+nh) - p  (fma(p,-1,s) == s-p, one rounding)
        ull s01 = f2x_add(f2x_add(ph01, ch01), nx.h01);
        ull s23 = f2x_add(f2x_add(ph23, ch23), nx.h23);
        ull pn01 = f2x_fma(cp01, NEG1_F2X, s01);
        ull pn23 = f2x_fma(cp23, NEG1_F2X, s23);
        float pn0, pn1, pn2, pn3;
        f2x_unpack(pn01, pn0, pn1);
        f2x_unpack(pn23, pn2, pn3);

        // gt structural for row y (integer, exact)
        unsigned vsum = htripP + htripC + htripN;
        unsigned csq  = spread4(gnibC);
        unsigned gcnt = vsum - csq;
        unsigned ge_m = nib_zero(gcnt ^ 0x1111u) & csq;
        unsigned gm_m = nib_zero(gcnt ^ 0x2222u) & csq;
        unsigned gj_m = (((gcnt >> 2) | (gcnt >> 3) | (gcnt & (gcnt >> 1))) & 0x1111u) & csq;

        // pred per-pixel classification
        unsigned pe_m = 0, pm_m = 0, pj_m = 0;
        {
            unsigned p0 = pnibC & 1u, p1 = (pnibC >> 1) & 1u;
            unsigned p2 = (pnibC >> 2) & 1u, p3 = (pnibC >> 3) & 1u;
            pe_m |= (p0 & (unsigned)(pn0 == 1.f));
            pm_m |= (p0 & (unsigned)(pn0 == 2.f));
            pj_m |= (p0 & (unsigned)(pn0 > 2.f));
            pe_m |= (p1 & (unsigned)(pn1 == 1.f)) << 4;
            pm_m |= (p1 & (unsigned)(pn1 == 2.f)) << 4;
            pj_m |= (p1 & (unsigned)(pn1 > 2.f)) << 4;
            pe_m |= (p2 & (unsigned)(pn2 == 1.f)) << 8;
            pm_m |= (p2 & (unsigned)(pn2 == 2.f)) << 8;
            pj_m |= (p2 & (unsigned)(pn2 > 2.f)) << 8;
            pe_m |= (p3 & (unsigned)(pn3 == 1.f)) << 12;
            pm_m |= (p3 & (unsigned)(pn3 == 2.f)) << 12;
            pj_m |= (p3 & (unsigned)(pn3 > 2.f)) << 12;
        }
        c[0] += __popc(pe_m); c[1] += __popc(ge_m); c[2] += __popc(pe_m & ge_m);
        c[3] += __popc(pm_m); c[4] += __popc(gm_m); c[5] += __popc(pm_m & gm_m);
        c[6] += __popc(pj_m); c[7] += __popc(gj_m); c[8] += __popc(pj_m & gj_m);

        // assemble 32-bit mask words over 8-lane nibble groups
        unsigned pw = pnibC << ((lane & 7) * 4);
        unsigned gw = gnibC << ((lane & 7) * 4);
        pw |= __shfl_xor_sync(0xffffffffu, pw, 1);
        gw |= __shfl_xor_sync(0xffffffffu, gw, 1);
        pw |= __shfl_xor_sync(0xffffffffu, pw, 2);
        gw |= __shfl_xor_sync(0xffffffffu, gw, 2);
        pw |= __shfl_xor_sync(0xffffffffu, pw, 4);
        gw |= __shfl_xor_sync(0xffffffffu, gw, 4);
        if ((lane & 7) == 0) {
            size_t widx = (size_t)(b * H + y) * WPR + cs * 4 + (lane >> 3);
            g_pmask[widx] = pw;
            g_gmask[widx] = gw;
        }

        // rotate pipelines
        ph01 = ch01; ph23 = ch23;
        ch01 = nx.h01; ch23 = nx.h23;
        cp01 = nx.p01; cp23 = nx.p23;
        cg01 = ng01;  cg23 = ng23;
        pnibC = pnibN;
        htripP = htripC; htripC = htripN; gnibC = gnibN;
        vP1 = vPn; vG1 = vGn;
    }

    // collapse packed accumulators
    float ai_lo, ai_hi, t2, t3;
    f2x_unpack(ai01, ai_lo, ai_hi);
    f2x_unpack(ai23, t2, t3);
    float a_i = (ai_lo + ai_hi) + (t2 + t3);
    f2x_unpack(ap01, ai_lo, ai_hi);
    f2x_unpack(ap23, t2, t3);
    float a_p = (ai_lo + ai_hi) + (t2 + t3);

    // warp reduce
    #pragma unroll
    for (int o = 16; o; o >>= 1) {
        a_i += __shfl_down_sync(0xffffffffu, a_i, o);
        a_p += __shfl_down_sync(0xffffffffu, a_p, o);
    }
    #pragma unroll
    for (int k = 0; k < 10; k++) {
        #pragma unroll
        for (int o = 16; o; o >>= 1) c[k] += __shfl_down_sync(0xffffffffu, c[k], o);
    }

    __shared__ float sf[2];
    __shared__ int   si[10];
    if (threadIdx.x < 2)  sf[threadIdx.x] = 0.f;
    if (threadIdx.x < 10) si[threadIdx.x] = 0;
    __syncthreads();
    if (lane == 0) {
        atomicAdd(&sf[0], a_i); atomicAdd(&sf[1], a_p);
        #pragma unroll
        for (int k = 0; k < 10; k++) atomicAdd(&si[k], c[k]);
    }
    __syncthreads();
    if (threadIdx.x < 2)  g_part[blockIdx.x][b][threadIdx.x] = sf[threadIdx.x];
    if (threadIdx.x >= 2 && threadIdx.x < 12)
        atomicAdd(&g_icnt[b][threadIdx.x - 2], si[threadIdx.x - 2]);   // exact int
}

// ======================= medial (unchanged from R15) =======================
__device__ __forceinline__ void load_q_row(const unsigned* __restrict__ rowp,
                                           int hq, unsigned* cur) {
    const uint4* q = reinterpret_cast<const uint4*>(rowp);
    uint4 a = q[hq];
    cur[0] = (hq > 0) ? rowp[hq * 4 - 1] : 0u;
    cur[1] = a.x; cur[2] = a.y; cur[3] = a.z; cur[4] = a.w;
    cur[5] = (hq < MCOL - 1) ? rowp[hq * 4 + 4] : 0u;
}
__device__ __forceinline__ void load_q_unc(const unsigned* __restrict__ rowp,
                                           int hq, unsigned* unc) {
    const uint4* q = reinterpret_cast<const uint4*>(rowp);
    uint4 a = q[hq];
    unc[0] = a.x; unc[1] = a.y; unc[2] = a.z; unc[3] = a.w;
}

__global__ void __launch_bounds__(MTHR, 12) medial_kernel(float* __restrict__ out) {
    const int lane = threadIdx.x & 31;
    const int wid  = threadIdx.x >> 5;
    const int sidx = blockIdx.x * MWPB + wid;
    const int strip = sidx >> 2;
    const int hq    = sidx & 3;
    const int b    = blockIdx.y >> 1;
    const int dir  = blockIdx.y & 1;
    const unsigned* ts = dir ? g_gmask : g_pmask;
    const unsigned* rs = dir ? g_pmask : g_gmask;

    const int base = strip * MINT - 9;
    const int r0 = base + 2 * lane;
    const int r1 = r0 + 1;
    const int i0 = strip * MINT, i1 = i0 + MINT;
    const bool v0 = ((unsigned)r0 < (unsigned)H);
    const bool v1 = ((unsigned)r1 < (unsigned)H);
    const bool in0 = v0 && (r0 >= i0) && (r0 < i1);
    const bool in1 = v1 && (r1 >= i0) && (r1 < i1);

    unsigned cur0[6], cur1[6], unc0[4], unc1[4];
    #pragma unroll
    for (int i = 0; i < 6; i++) { cur0[i] = 0u; cur1[i] = 0u; }
    #pragma unroll
    for (int i = 0; i < 4; i++) { unc0[i] = 0u; unc1[i] = 0u; }

    if (v0)  load_q_row(rs + ((size_t)b * H + r0) * WPR, hq, cur0);
    if (v1)  load_q_row(rs + ((size_t)b * H + r1) * WPR, hq, cur1);
    if (in0) load_q_unc(ts + ((size_t)b * H + r0) * WPR, hq, unc0);
    if (in1) load_q_unc(ts + ((size_t)b * H + r1) * WPR, hq, unc1);

    int cnt = 0, notcov = 0;
    #pragma unroll
    for (int i = 0; i < 4; i++) cnt += __popc(unc0[i]) + __popc(unc1[i]);

    unsigned any = unc0[0] | unc0[1] | unc0[2] | unc0[3]
                 | unc1[0] | unc1[1] | unc1[2] | unc1[3];
    if (!__all_sync(0xffffffffu, any == 0u)) {
        for (int d = 1; d <= 9; d++) {
            unsigned p0 = 0u, p1 = 0u;
            #pragma unroll
            for (int i = 0; i < 6; i++) {
                unsigned o0 = cur0[i], o1 = cur1[i];
                unsigned n0 = (i < 5) ? cur0[i + 1] : 0u;
                unsigned n1 = (i < 5) ? cur1[i + 1] : 0u;
                cur0[i] = o0 | (o0 << 1) | (o0 >> 1) | (p0 >> 31) | (n0 << 31);
                cur1[i] = o1 | (o1 << 1) | (o1 >> 1) | (p1 >> 31) | (n1 << 31);
                p0 = o0; p1 = o1;
            }
            #pragma unroll
            for (int i = 0; i < 6; i++) {
                unsigned h0 = cur0[i], h1 = cur1[i];
                unsigned up = __shfl_up_sync(0xffffffffu, h1, 1);
                unsigned dn = __shfl_down_sync(0xffffffffu, h0, 1);
                up = (lane == 0)  ? 0u : up;
                dn = (lane == 31) ? 0u : dn;
                cur0[i] = h0 | up | h1;
                cur1[i] = h1 | h0 | dn;
            }
            any = 0u;
            #pragma unroll
            for (int i = 0; i < 4; i++) {
                unc0[i] &= ~cur0[i + 1];
                unc1[i] &= ~cur1[i + 1];
                notcov += __popc(unc0[i]) + __popc(unc1[i]);
                any |= unc0[i] | unc1[i];
            }
            if (__all_sync(0xffffffffu, any == 0u)) break;
        }
    }

    int dist = cnt + notcov;
    #pragma unroll
    for (int o = 16; o; o >>= 1) {
        dist += __shfl_down_sync(0xffffffffu, dist, o);
        cnt  += __shfl_down_sync(0xffffffffu, cnt, o);
    }
    __shared__ int sred[MWPB][2];
    if (lane == 0) { sred[wid][0] = dist; sred[wid][1] = cnt; }
    __syncthreads();

    __shared__ bool isLast;
    if (threadIdx.x == 0) {
        int D = sred[0][0] + sred[1][0];
        int C = sred[0][1] + sred[1][1];
        atomicAdd(&g_msum[b][dir], D);
        atomicAdd(&g_mc[b][dir], C);
        __threadfence();
        int old = atomicAdd(&g_done, 1);
        isLast = (old == MEDIAL_BLOCKS - 1);
    }
    __syncthreads();
    if (!isLast) return;
    __threadfence();

    // ---- fused finalize (64 threads) ----
    __shared__ float accf[B][2];
    __shared__ float sd[B], ss[B], sm2[B];
    int t = threadIdx.x;
    {
        int bb = t >> 1, k = t & 1;
        float s = 0.f;
        #pragma unroll
        for (int i = 0; i < GX; i++) s += g_part[i][bb][k];
        accf[bb][k] = s;
    }
    __syncthreads();

    if (t < B) {
        int bb = t;
        float inter = accf[bb][0], ps = accf[bb][1];
        float gs = (float)g_icnt[bb][9];
        float dice = (2.f * inter + 1.f) / (ps + gs + 1.f);

        float pe = (float)g_icnt[bb][0], ge = (float)g_icnt[bb][1], ie = (float)g_icnt[bb][2];
        float pm = (float)g_icnt[bb][3], gm = (float)g_icnt[bb][4], im = (float)g_icnt[bb][5];
        float pj = (float)g_icnt[bb][6], gj = (float)g_icnt[bb][7], ij = (float)g_icnt[bb][8];
        float e_iou = (ie + 1.f) / (pe + ge - ie + 1.f);
        float m_iou = (im + 1.f) / (pm + gm - im + 1.f);
        float j_iou = (ij + 1.f) / (pj + gj - ij + 1.f);
        float total = ge + gj + gm + 1.f;
        float sl = 1.f - ((ge / total) * e_iou + (gj / total) * j_iou + (gm / total) * m_iou);

        float p2g = (float)g_msum[bb][0] / ((float)g_mc[bb][0] + 1.f);
        float g2p = (float)g_msum[bb][1] / ((float)g_mc[bb][1] + 1.f);
        float med = ((p2g + g2p) * 0.5f) / 10.f;

        sd[bb] = dice; ss[bb] = sl; sm2[bb] = med;
    }
    __syncthreads();

    for (int idx = t; idx < B * 10; idx += MTHR) ((int*)g_icnt)[idx] = 0;
    ((int*)g_msum)[t] = 0;
    ((int*)g_mc)[t]   = 0;

    if (t == 0) {
        float d = 0.f, s = 0.f, m = 0.f;
        for (int i = 0; i < B; i++) { d += sd[i]; s += ss[i]; m += sm2[i]; }
        d *= (1.f / B); s *= (1.f / B); m *= (1.f / B);
        float dl = 1.f - d;
        float avg = (dl + s + m) / 3.f;
        out[0] = dl / (dl + 1.f) * avg + s / (s + 1.f) * avg + m / (m + 1.f) * avg;
        g_done = 0;
    }
}

extern "C" void kernel_launch(void* const* d_in, const int* in_sizes, int n_in,
                              void* d_out, int out_size) {
    const float* pred = (const float*)d_in[0];
    const float* gt   = (const float*)d_in[1];
    float* out = (float*)d_out;
    (void)in_sizes; (void)n_in; (void)out_size;

    stats_kernel<<<dim3(GX, B), 128>>>(pred, gt);
    medial_kernel<<<dim3(MGX, B * 2), MTHR>>>(out);
}